// round 4
// baseline (speedup 1.0000x reference)
#include <cuda_runtime.h>
#include <cstdint>

// WholeMask R4: low-instruction + high-occupancy.
// Warp = 128-column quarter x 32 contiguous rows. Per-row sy is warp-uniform
// and changes rarely (run-length ~h/28 rows), so the float4 value is
// recomputed only on sy-change; steady state = LDS.U8 + STG.128 per row.
// smem ~3.7KB -> occupancy not smem-limited; grid 128x8 small CTAs for balance.

#define MH 28
#define MW 28
#define IMG 512

__global__ __launch_bounds__(256, 6)
void wholemask_kernel(const float* __restrict__ bboxess,
                      const int*   __restrict__ counts,
                      const float* __restrict__ maskss,
                      float*       __restrict__ out,
                      int Kk)
{
    __shared__ float smask[MH * MW];          // 3136 B
    __shared__ unsigned char srow[IMG];       // 512 B: sy per y, 28 = zero-row

    const int slice = blockIdx.x;             // b*K + k
    const int b = slice / Kk;
    const int k = slice - b * Kk;
    const int tid = threadIdx.x;              // 0..255

    const bool valid = (k < counts[b]);

    // Rounded (half-even == jnp.round) + clipped box.
    const float4 bb = reinterpret_cast<const float4*>(bboxess)[slice];
    int y1 = __float2int_rn(bb.x);
    int x1 = __float2int_rn(bb.y);
    int y2 = __float2int_rn(bb.z);
    int x2 = __float2int_rn(bb.w);
    y1 = min(max(y1, 0), IMG - 1);
    x1 = min(max(x1, 0), IMG - 1);
    y2 = min(max(y2, y1 + 1), IMG);
    x2 = min(max(x2, x1 + 1), IMG);
    const int h = y2 - y1;
    const int w = x2 - x1;

    // ---- Setup ----
    {   // mask tile -> shared
        const float* gm = maskss + (size_t)slice * (MH * MW);
        for (int i = tid; i < MH * MW; i += 256)
            smask[i] = gm[i];
        // per-row sy LUT (2 rows per thread); 28 = sentinel (zero row)
        for (int y = tid; y < IMG; y += 256) {
            const bool iny = valid && (y >= y1) && (y < y2);
            int sy = (y - y1) * MH / h;       // y>=y1 inside -> trunc==floor
            sy = min(max(sy, 0), MH - 1);
            srow[y] = (unsigned char)(iny ? sy : MH);
        }
    }

    // Per-thread column setup (registers).
    const int lane = tid & 31;
    const int wrp  = tid >> 5;                // 0..7
    const int q    = wrp & 3;                 // column quarter
    const int band = wrp >> 2;                // row band 0..1
    const int x0   = q * 128 + lane * 4;

    int  sx[4];
    bool inx[4];
    #pragma unroll
    for (int c = 0; c < 4; ++c) {
        const int x = x0 + c;
        inx[c] = (x >= x1) && (x < x2);
        int s = (x - x1) * MW / w;
        sx[c] = min(max(s, 0), MW - 1);
    }
    __syncthreads();

    // ---- Main: 32 contiguous rows per warp ----
    const int ybase = blockIdx.y * 64 + band * 32;
    float* op = out + (size_t)slice * (IMG * IMG) + (size_t)ybase * IMG + x0;

    int   prev = -1;
    float4 v = make_float4(0.f, 0.f, 0.f, 0.f);

    #pragma unroll 4
    for (int r = 0; r < 32; ++r) {
        const int syv = srow[ybase + r];      // warp-uniform broadcast
        if (syv != prev) {                    // warp-uniform branch, rare
            prev = syv;
            if (syv == MH) {
                v = make_float4(0.f, 0.f, 0.f, 0.f);
            } else {
                const float* mrow = smask + syv * MW;
                v.x = inx[0] ? mrow[sx[0]] : 0.f;
                v.y = inx[1] ? mrow[sx[1]] : 0.f;
                v.z = inx[2] ? mrow[sx[2]] : 0.f;
                v.w = inx[3] ? mrow[sx[3]] : 0.f;
            }
        }
        *reinterpret_cast<float4*>(op) = v;
        op += IMG;
    }
}

extern "C" void kernel_launch(void* const* d_in, const int* in_sizes, int n_in,
                              void* d_out, int out_size)
{
    const float* bboxess = (const float*)d_in[0];   // (B,K,4) f32
    const int*   counts  = (const int*)  d_in[1];   // (B,1)   i32
    const float* maskss  = (const float*)d_in[2];   // (B,K,1,28,28) f32

    const int BK = in_sizes[0] / 4;                 // B*K
    const int Bv = in_sizes[1];                     // B
    const int Kk = BK / Bv;                         // K

    dim3 block(256);
    dim3 grid(BK, IMG / 64);       // 128 slices x 8 chunks = 1024 CTAs
    wholemask_kernel<<<grid, block>>>(bboxess, counts, maskss,
                                      (float*)d_out, Kk);
}

// round 5
// speedup vs baseline: 1.0829x; 1.0829x over previous
#include <cuda_runtime.h>
#include <cstdint>

// WholeMask R5: R1's winning store policy (__stcs evict-first; every line
// must evict at steady state anyway) + R4's run-cached near-zero inner loop.
// Block 512 = 4 column-quarters x 4 bands of 16 contiguous rows. Warp-uniform
// sy changes rarely -> float4 value recomputed only on change; steady state
// is LDS.U8(broadcast) + ISETP + STG.128.CS + IADD per 512B/warp.

#define MH 28
#define MW 28
#define IMG 512

__global__ __launch_bounds__(512, 3)
void wholemask_kernel(const float* __restrict__ bboxess,
                      const int*   __restrict__ counts,
                      const float* __restrict__ maskss,
                      float*       __restrict__ out,
                      int Kk)
{
    __shared__ float smask[MH * MW];          // 3136 B
    __shared__ unsigned char srow[IMG];       // 512 B: sy per y, 28 = zero-row

    const int slice = blockIdx.x;             // b*K + k
    const int b = slice / Kk;
    const int k = slice - b * Kk;
    const int tid = threadIdx.y * blockDim.x + threadIdx.x;   // 0..511

    const bool valid = (k < counts[b]);

    // Rounded (half-even == jnp.round) + clipped box.
    const float4 bb = reinterpret_cast<const float4*>(bboxess)[slice];
    int y1 = __float2int_rn(bb.x);
    int x1 = __float2int_rn(bb.y);
    int y2 = __float2int_rn(bb.z);
    int x2 = __float2int_rn(bb.w);
    y1 = min(max(y1, 0), IMG - 1);
    x1 = min(max(x1, 0), IMG - 1);
    y2 = min(max(y2, y1 + 1), IMG);
    x2 = min(max(x2, x1 + 1), IMG);
    const int h = y2 - y1;
    const int w = x2 - x1;

    // ---- Setup ----
    {   // mask tile -> shared (784 elems, 512 threads -> 2 strided passes)
        const float* gm = maskss + (size_t)slice * (MH * MW);
        for (int i = tid; i < MH * MW; i += 512)
            smask[i] = gm[i];
        // per-row sy LUT; 28 = sentinel (zero row). One row per thread.
        {
            const int y = tid;
            const bool iny = valid && (y >= y1) && (y < y2);
            int sy = (y - y1) * MH / h;       // y>=y1 inside -> trunc==floor
            sy = min(max(sy, 0), MH - 1);
            srow[y] = (unsigned char)(iny ? sy : MH);
        }
    }

    // Per-thread column setup (registers).
    const int lane = threadIdx.x & 31;
    const int q    = threadIdx.x >> 5;        // column quarter 0..3
    const int band = threadIdx.y;             // row band 0..3 (16 rows each)
    const int x0   = q * 128 + lane * 4;

    int  sx[4];
    bool inx[4];
    #pragma unroll
    for (int c = 0; c < 4; ++c) {
        const int x = x0 + c;
        inx[c] = (x >= x1) && (x < x2);
        int s = (x - x1) * MW / w;
        sx[c] = min(max(s, 0), MW - 1);
    }
    __syncthreads();

    // ---- Main: 16 contiguous rows per warp ----
    const int ybase = blockIdx.y * 64 + band * 16;
    float* op = out + (size_t)slice * (IMG * IMG) + (size_t)ybase * IMG + x0;

    int    prev = -1;
    float4 v = make_float4(0.f, 0.f, 0.f, 0.f);

    #pragma unroll
    for (int r = 0; r < 16; ++r) {
        const int syv = srow[ybase + r];      // warp-uniform broadcast
        if (syv != prev) {                    // warp-uniform, rare
            prev = syv;
            if (syv == MH) {
                v = make_float4(0.f, 0.f, 0.f, 0.f);
            } else {
                const float* mrow = smask + syv * MW;
                v.x = inx[0] ? mrow[sx[0]] : 0.f;
                v.y = inx[1] ? mrow[sx[1]] : 0.f;
                v.z = inx[2] ? mrow[sx[2]] : 0.f;
                v.w = inx[3] ? mrow[sx[3]] : 0.f;
            }
        }
        __stcs(reinterpret_cast<float4*>(op), v);   // evict-first streaming
        op += IMG;
    }
}

extern "C" void kernel_launch(void* const* d_in, const int* in_sizes, int n_in,
                              void* d_out, int out_size)
{
    const float* bboxess = (const float*)d_in[0];   // (B,K,4) f32
    const int*   counts  = (const int*)  d_in[1];   // (B,1)   i32
    const float* maskss  = (const float*)d_in[2];   // (B,K,1,28,28) f32

    const int BK = in_sizes[0] / 4;                 // B*K
    const int Bv = in_sizes[1];                     // B
    const int Kk = BK / Bv;                         // K

    dim3 block(128, 4);            // 16 warps: 4 quarters x 4 bands
    dim3 grid(BK, IMG / 64);       // 128 slices x 8 chunks = 1024 CTAs
    wholemask_kernel<<<grid, block>>>(bboxess, counts, maskss,
                                      (float*)d_out, Kk);
}